// round 1
// baseline (speedup 1.0000x reference)
#include <cuda_runtime.h>

#define BB   4
#define SS   4096
#define DIN  1024
#define DH   64
#define MROWS (BB*SS)

// Scratch for projected Q, K, V  (rows = b*SS + s, cols = DH), 4 MB each.
__device__ float g_Q[MROWS * DH];
__device__ float g_K[MROWS * DH];
__device__ float g_V[MROWS * DH];

// ---------------------------------------------------------------------------
// Kernel 1: fused QKV projection   out = relu(X @ W + b)
// Grid: (MROWS/64, 3).  blockIdx.y selects which of Q/K/V.
// Tile: 64 rows x 64 cols, BK = 32.  256 threads (16x16), 4x4 micro-tile.
// ---------------------------------------------------------------------------
__global__ __launch_bounds__(256) void qkv_kernel(
    const float* __restrict__ X,
    const float* __restrict__ Wq, const float* __restrict__ bq,
    const float* __restrict__ Wk, const float* __restrict__ bk,
    const float* __restrict__ Wv, const float* __restrict__ bv)
{
    const float* W; const float* bias; float* out;
    if (blockIdx.y == 0)      { W = Wq; bias = bq; out = g_Q; }
    else if (blockIdx.y == 1) { W = Wk; bias = bk; out = g_K; }
    else                      { W = Wv; bias = bv; out = g_V; }

    __shared__ float Xs[64][33];   // padded: conflict-free staging + broadcast frags
    __shared__ float Ws[32][64];   // natural: float4 frags conflict-free

    const int t  = threadIdx.x;
    const int tx = t & 15;
    const int ty = t >> 4;
    const int m0 = blockIdx.x * 64;

    float c[4][4] = {};

    for (int k0 = 0; k0 < DIN; k0 += 32) {
        // stage X tile 64x32 (float4 gmem reads, scalar smem writes)
        #pragma unroll
        for (int u = 0; u < 2; u++) {
            int cidx = t + 256 * u;          // 0..511 float4 chunks
            int row  = cidx >> 3;            // 0..63
            int c4   = cidx & 7;             // 0..7
            float4 v = *(const float4*)&X[(m0 + row) * DIN + k0 + c4 * 4];
            Xs[row][c4 * 4 + 0] = v.x;
            Xs[row][c4 * 4 + 1] = v.y;
            Xs[row][c4 * 4 + 2] = v.z;
            Xs[row][c4 * 4 + 3] = v.w;
        }
        // stage W tile 32x64 (float4 all the way)
        #pragma unroll
        for (int u = 0; u < 2; u++) {
            int cidx = t + 256 * u;          // 0..511
            int row  = cidx >> 4;            // 0..31
            int c4   = cidx & 15;            // 0..15
            *(float4*)&Ws[row][c4 * 4] = *(const float4*)&W[(k0 + row) * DH + c4 * 4];
        }
        __syncthreads();

        #pragma unroll
        for (int k = 0; k < 32; k++) {
            float a0 = Xs[4 * ty + 0][k];
            float a1 = Xs[4 * ty + 1][k];
            float a2 = Xs[4 * ty + 2][k];
            float a3 = Xs[4 * ty + 3][k];
            float4 w4 = *(const float4*)&Ws[k][4 * tx];
            c[0][0] = fmaf(a0, w4.x, c[0][0]); c[0][1] = fmaf(a0, w4.y, c[0][1]);
            c[0][2] = fmaf(a0, w4.z, c[0][2]); c[0][3] = fmaf(a0, w4.w, c[0][3]);
            c[1][0] = fmaf(a1, w4.x, c[1][0]); c[1][1] = fmaf(a1, w4.y, c[1][1]);
            c[1][2] = fmaf(a1, w4.z, c[1][2]); c[1][3] = fmaf(a1, w4.w, c[1][3]);
            c[2][0] = fmaf(a2, w4.x, c[2][0]); c[2][1] = fmaf(a2, w4.y, c[2][1]);
            c[2][2] = fmaf(a2, w4.z, c[2][2]); c[2][3] = fmaf(a2, w4.w, c[2][3]);
            c[3][0] = fmaf(a3, w4.x, c[3][0]); c[3][1] = fmaf(a3, w4.y, c[3][1]);
            c[3][2] = fmaf(a3, w4.z, c[3][2]); c[3][3] = fmaf(a3, w4.w, c[3][3]);
        }
        __syncthreads();
    }

    // epilogue: + bias, relu, store
    float4 bi = *(const float4*)&bias[4 * tx];
    #pragma unroll
    for (int i = 0; i < 4; i++) {
        float4 r;
        r.x = fmaxf(c[i][0] + bi.x, 0.f);
        r.y = fmaxf(c[i][1] + bi.y, 0.f);
        r.z = fmaxf(c[i][2] + bi.z, 0.f);
        r.w = fmaxf(c[i][3] + bi.w, 0.f);
        *(float4*)&out[(m0 + 4 * ty + i) * DH + 4 * tx] = r;
    }
}

// ---------------------------------------------------------------------------
// Kernel 2: flash attention with online softmax (no scaling), mask epilogue.
// Grid: (SS/64, BB).  Block: 64 queries x full D=64, streaming 64-key tiles.
// 256 threads (16x16), 4x4 micro-tiles for both S = Q@K^T and O = P@V.
// ---------------------------------------------------------------------------
__global__ __launch_bounds__(256) void attn_kernel(
    const float* __restrict__ mask, float* __restrict__ out)
{
    extern __shared__ float sm[];
    float* Qst = sm;                    // [64][68]  transposed: Qst[d][qr]
    float* Ks  = Qst + 64 * 68;         // [64][65]  natural:    Ks[kc][d]
    float* Vs  = Ks  + 64 * 65;         // [64][64]  natural:    Vs[kk][dc]
    float* Ps  = Vs  + 64 * 64;         // [64][68]  natural:    Ps[qr][kc]

    const int t  = threadIdx.x;
    const int tx = t & 15;
    const int ty = t >> 4;
    const int b  = blockIdx.y;
    const int q0 = blockIdx.x * 64;
    const int base = b * SS;

    // stage Q tile transposed (once per block)
    #pragma unroll
    for (int u = 0; u < 4; u++) {
        int cidx = t + 256 * u;          // 0..1023 float4 chunks
        int row  = cidx >> 4;            // query row 0..63
        int c4   = cidx & 15;            // d chunk 0..15
        float4 v = *(const float4*)&g_Q[(base + q0 + row) * DH + c4 * 4];
        Qst[(c4 * 4 + 0) * 68 + row] = v.x;
        Qst[(c4 * 4 + 1) * 68 + row] = v.y;
        Qst[(c4 * 4 + 2) * 68 + row] = v.z;
        Qst[(c4 * 4 + 3) * 68 + row] = v.w;
    }

    float o[4][4] = {};
    float mrow[4] = { -1e30f, -1e30f, -1e30f, -1e30f };
    float lrow[4] = {};

    for (int kt = 0; kt < SS / 64; kt++) {
        __syncthreads();   // protects Ks/Vs/Ps from previous iteration's readers
        const int k0 = kt * 64;
        #pragma unroll
        for (int u = 0; u < 4; u++) {
            int cidx = t + 256 * u;
            int row  = cidx >> 4;
            int c4   = cidx & 15;
            float4 v = *(const float4*)&g_K[(base + k0 + row) * DH + c4 * 4];
            Ks[row * 65 + c4 * 4 + 0] = v.x;
            Ks[row * 65 + c4 * 4 + 1] = v.y;
            Ks[row * 65 + c4 * 4 + 2] = v.z;
            Ks[row * 65 + c4 * 4 + 3] = v.w;
            float4 w = *(const float4*)&g_V[(base + k0 + row) * DH + c4 * 4];
            *(float4*)&Vs[row * 64 + c4 * 4] = w;
        }
        __syncthreads();

        // S = Q @ K^T   (4x4 per thread: rows 4ty.., cols 4tx..)
        float s[4][4] = {};
        #pragma unroll 16
        for (int d = 0; d < 64; d++) {
            float4 q = *(const float4*)&Qst[d * 68 + 4 * ty];
            float k0v = Ks[(4 * tx + 0) * 65 + d];
            float k1v = Ks[(4 * tx + 1) * 65 + d];
            float k2v = Ks[(4 * tx + 2) * 65 + d];
            float k3v = Ks[(4 * tx + 3) * 65 + d];
            s[0][0] = fmaf(q.x, k0v, s[0][0]); s[0][1] = fmaf(q.x, k1v, s[0][1]);
            s[0][2] = fmaf(q.x, k2v, s[0][2]); s[0][3] = fmaf(q.x, k3v, s[0][3]);
            s[1][0] = fmaf(q.y, k0v, s[1][0]); s[1][1] = fmaf(q.y, k1v, s[1][1]);
            s[1][2] = fmaf(q.y, k2v, s[1][2]); s[1][3] = fmaf(q.y, k3v, s[1][3]);
            s[2][0] = fmaf(q.z, k0v, s[2][0]); s[2][1] = fmaf(q.z, k1v, s[2][1]);
            s[2][2] = fmaf(q.z, k2v, s[2][2]); s[2][3] = fmaf(q.z, k3v, s[2][3]);
            s[3][0] = fmaf(q.w, k0v, s[3][0]); s[3][1] = fmaf(q.w, k1v, s[3][1]);
            s[3][2] = fmaf(q.w, k2v, s[3][2]); s[3][3] = fmaf(q.w, k3v, s[3][3]);
        }

        // online softmax update (row stats shared across the 16-lane tx group)
        #pragma unroll
        for (int i = 0; i < 4; i++) {
            float mi = fmaxf(fmaxf(s[i][0], s[i][1]), fmaxf(s[i][2], s[i][3]));
            #pragma unroll
            for (int off = 8; off >= 1; off >>= 1)
                mi = fmaxf(mi, __shfl_xor_sync(0xffffffffu, mi, off));
            float mnew  = fmaxf(mrow[i], mi);
            float scale = __expf(mrow[i] - mnew);
            mrow[i] = mnew;
            float li = 0.f;
            #pragma unroll
            for (int j = 0; j < 4; j++) {
                s[i][j] = __expf(s[i][j] - mnew);
                li += s[i][j];
            }
            #pragma unroll
            for (int off = 8; off >= 1; off >>= 1)
                li += __shfl_xor_sync(0xffffffffu, li, off);
            lrow[i] = lrow[i] * scale + li;
            o[i][0] *= scale; o[i][1] *= scale; o[i][2] *= scale; o[i][3] *= scale;
            *(float4*)&Ps[(4 * ty + i) * 68 + 4 * tx] =
                make_float4(s[i][0], s[i][1], s[i][2], s[i][3]);
        }
        __syncthreads();

        // O += P @ V   (rows 4ty.., d-cols 4tx..)
        #pragma unroll 16
        for (int kk = 0; kk < 64; kk++) {
            float p0 = Ps[(4 * ty + 0) * 68 + kk];
            float p1 = Ps[(4 * ty + 1) * 68 + kk];
            float p2 = Ps[(4 * ty + 2) * 68 + kk];
            float p3 = Ps[(4 * ty + 3) * 68 + kk];
            float4 v = *(const float4*)&Vs[kk * 64 + 4 * tx];
            o[0][0] = fmaf(p0, v.x, o[0][0]); o[0][1] = fmaf(p0, v.y, o[0][1]);
            o[0][2] = fmaf(p0, v.z, o[0][2]); o[0][3] = fmaf(p0, v.w, o[0][3]);
            o[1][0] = fmaf(p1, v.x, o[1][0]); o[1][1] = fmaf(p1, v.y, o[1][1]);
            o[1][2] = fmaf(p1, v.z, o[1][2]); o[1][3] = fmaf(p1, v.w, o[1][3]);
            o[2][0] = fmaf(p2, v.x, o[2][0]); o[2][1] = fmaf(p2, v.y, o[2][1]);
            o[2][2] = fmaf(p2, v.z, o[2][2]); o[2][3] = fmaf(p2, v.w, o[2][3]);
            o[3][0] = fmaf(p3, v.x, o[3][0]); o[3][1] = fmaf(p3, v.y, o[3][1]);
            o[3][2] = fmaf(p3, v.z, o[3][2]); o[3][3] = fmaf(p3, v.w, o[3][3]);
        }
    }

    // epilogue: normalize by l, apply mask (mask is [B,S,1], broadcast over D)
    #pragma unroll
    for (int i = 0; i < 4; i++) {
        int q = q0 + 4 * ty + i;
        float mv  = mask[base + q];
        float inv = mv / lrow[i];
        float4 r = make_float4(o[i][0] * inv, o[i][1] * inv,
                               o[i][2] * inv, o[i][3] * inv);
        *(float4*)&out[(size_t)(base + q) * DH + 4 * tx] = r;
    }
}

// ---------------------------------------------------------------------------
extern "C" void kernel_launch(void* const* d_in, const int* in_sizes, int n_in,
                              void* d_out, int out_size)
{
    const float* X    = (const float*)d_in[0];
    const float* mask = (const float*)d_in[1];
    const float* Wq   = (const float*)d_in[2];
    const float* bq   = (const float*)d_in[3];
    const float* Wk   = (const float*)d_in[4];
    const float* bk   = (const float*)d_in[5];
    const float* Wv   = (const float*)d_in[6];
    const float* bv   = (const float*)d_in[7];

    const int smem_attn = (64 * 68 + 64 * 65 + 64 * 64 + 64 * 68) * sizeof(float); // 67840
    cudaFuncSetAttribute(attn_kernel,
                         cudaFuncAttributeMaxDynamicSharedMemorySize, smem_attn);

    qkv_kernel<<<dim3(MROWS / 64, 3), 256>>>(X, Wq, bq, Wk, bk, Wv, bv);
    attn_kernel<<<dim3(SS / 64, BB), 256, smem_attn>>>(mask, (float*)d_out);
}

// round 2
// speedup vs baseline: 1.0208x; 1.0208x over previous
#include <cuda_runtime.h>

#define BB   4
#define SS   4096
#define DIN  1024
#define DH   64
#define MROWS (BB*SS)

__device__ float g_Q[MROWS * DH];
__device__ float g_K[MROWS * DH];
__device__ float g_V[MROWS * DH];

typedef unsigned long long u64;

// packed fp32x2 FMA: c.lo += a.lo*b.lo ; c.hi += a.hi*b.hi
__device__ __forceinline__ void fma2(u64& c, u64 a, u64 b) {
    asm("fma.rn.f32x2 %0, %1, %2, %0;" : "+l"(c) : "l"(a), "l"(b));
}
__device__ __forceinline__ float fold2(u64 v) {
    float lo, hi;
    asm("mov.b64 {%0, %1}, %2;" : "=f"(lo), "=f"(hi) : "l"(v));
    return lo + hi;
}

// ---------------------------------------------------------------------------
// Kernel 1: fused QKV projection  out = relu(X @ W + b), f32x2 packed over k.
// Tile 64 rows x 64 cols, BK=64. 256 threads (16x16), micro 4x4.
// W staged transposed + XOR-swizzled 16B chunks (conflict-free LDS.128).
// ---------------------------------------------------------------------------
__global__ __launch_bounds__(256, 2) void qkv_kernel(
    const float* __restrict__ X,
    const float* __restrict__ Wq, const float* __restrict__ bq,
    const float* __restrict__ Wk, const float* __restrict__ bk,
    const float* __restrict__ Wv, const float* __restrict__ bv)
{
    const float* W; const float* bias; float* out;
    if (blockIdx.y == 0)      { W = Wq; bias = bq; out = g_Q; }
    else if (blockIdx.y == 1) { W = Wk; bias = bk; out = g_K; }
    else                      { W = Wv; bias = bv; out = g_V; }

    __shared__ float Xs[64 * 68];     // natural [row][k], stride 68
    __shared__ float Wst[64 * 64];    // [n][k-chunks swizzled], stride 64

    const int t  = threadIdx.x;
    const int tx = t & 15;
    const int ty = t >> 4;
    const int m0 = blockIdx.x * 64;

    u64 acc[4][4] = {};

    for (int k0 = 0; k0 < DIN; k0 += 64) {
        __syncthreads();
        // stage X tile 64x64 natural
        #pragma unroll
        for (int u = 0; u < 4; u++) {
            int cidx = t + 256 * u;
            int row  = cidx >> 4;
            int c4   = cidx & 15;
            *(float4*)&Xs[row * 68 + c4 * 4] =
                *(const float4*)&X[(m0 + row) * DIN + k0 + c4 * 4];
        }
        // stage W transposed: element W[k][n] -> Wst[n][ ((k>>2)^(n>>2))*4 + (k&3) ]
        #pragma unroll
        for (int u = 0; u < 4; u++) {
            int cidx = t + 256 * u;
            int kr   = cidx >> 4;          // k row 0..63
            int c4   = cidx & 15;          // n chunk 0..15
            float4 wv = *(const float4*)&W[(k0 + kr) * DH + c4 * 4];
            int chunk = (kr >> 2) ^ c4;    // n>>2 == c4 for all 4 cols below
            int word  = kr & 3;
            Wst[(4 * c4 + 0) * 64 + (chunk << 2) + word] = wv.x;
            Wst[(4 * c4 + 1) * 64 + (chunk << 2) + word] = wv.y;
            Wst[(4 * c4 + 2) * 64 + (chunk << 2) + word] = wv.z;
            Wst[(4 * c4 + 3) * 64 + (chunk << 2) + word] = wv.w;
        }
        __syncthreads();

        #pragma unroll 4
        for (int dc = 0; dc < 16; dc++) {
            u64 xp[4][2], wp[4][2];
            #pragma unroll
            for (int j = 0; j < 4; j++) {
                ulonglong2 wv = *(const ulonglong2*)&Wst[(4 * tx + j) * 64 + ((dc ^ tx) << 2)];
                wp[j][0] = wv.x; wp[j][1] = wv.y;
            }
            #pragma unroll
            for (int i = 0; i < 4; i++) {
                ulonglong2 xv = *(const ulonglong2*)&Xs[(4 * ty + i) * 68 + dc * 4];
                xp[i][0] = xv.x; xp[i][1] = xv.y;
            }
            #pragma unroll
            for (int i = 0; i < 4; i++)
                #pragma unroll
                for (int j = 0; j < 4; j++) {
                    fma2(acc[i][j], xp[i][0], wp[j][0]);
                    fma2(acc[i][j], xp[i][1], wp[j][1]);
                }
        }
    }

    float4 bi = *(const float4*)&bias[4 * tx];
    #pragma unroll
    for (int i = 0; i < 4; i++) {
        float4 r;
        r.x = fmaxf(fold2(acc[i][0]) + bi.x, 0.f);
        r.y = fmaxf(fold2(acc[i][1]) + bi.y, 0.f);
        r.z = fmaxf(fold2(acc[i][2]) + bi.z, 0.f);
        r.w = fmaxf(fold2(acc[i][3]) + bi.w, 0.f);
        *(float4*)&out[(m0 + 4 * ty + i) * DH + 4 * tx] = r;
    }
}

// ---------------------------------------------------------------------------
// Kernel 2: flash attention, f32x2 packed over reduction dims.
// Bq=128, Bk=64. 256 threads (16x16), micro 8 q-rows x 4 cols.
// Layouts: Qs/Ps natural (stride 68), Ks/Vst transposed-chunk XOR-swizzled.
// ---------------------------------------------------------------------------
__global__ __launch_bounds__(256, 1) void attn_kernel(
    const float* __restrict__ mask, float* __restrict__ out)
{
    extern __shared__ float sm[];
    float* Qs  = sm;                 // [128][68]  natural  Qs[r][d]
    float* Ks  = Qs  + 128 * 68;     // [64][64]   K[kc][d] chunks swizzled
    float* Vst = Ks  + 64 * 64;      // [64][64]   V^T: row=dcol, chunks over kk swizzled
    float* Ps  = Vst + 64 * 64;      // [128][68]  natural  Ps[r][kk]

    const int t  = threadIdx.x;
    const int tx = t & 15;
    const int ty = t >> 4;
    const int b  = blockIdx.y;
    const int q0 = blockIdx.x * 128;
    const int base = b * SS;

    // stage Q (once): natural layout
    #pragma unroll
    for (int u = 0; u < 8; u++) {
        int cidx = t + 256 * u;          // 0..2047
        int row  = cidx >> 4;            // 0..127
        int c4   = cidx & 15;
        *(float4*)&Qs[row * 68 + c4 * 4] =
            *(const float4*)&g_Q[(base + q0 + row) * DH + c4 * 4];
    }

    float o[8][4] = {};
    float mrow[8], lrow[8] = {};
    #pragma unroll
    for (int i = 0; i < 8; i++) mrow[i] = -1e30f;

    for (int kt = 0; kt < SS / 64; kt++) {
        const int k0 = kt * 64;
        __syncthreads();   // prior readers of Ks/Vst/Ps done
        // stage K: element K[kc][d] -> Ks[kc*64 + ((d>>2 ^ kc>>2)<<2) + (d&3)]
        #pragma unroll
        for (int u = 0; u < 4; u++) {
            int cidx = t + 256 * u;
            int kc   = cidx >> 4;
            int c4   = cidx & 15;
            float4 kv = *(const float4*)&g_K[(base + k0 + kc) * DH + c4 * 4];
            *(float4*)&Ks[kc * 64 + ((c4 ^ (kc >> 2)) << 2)] = kv;
        }
        // stage V transposed: V[kk][j] -> Vst[j*64 + ((kk>>2 ^ j>>2)<<2) + (kk&3)]
        #pragma unroll
        for (int u = 0; u < 4; u++) {
            int cidx = t + 256 * u;
            int kk   = cidx >> 4;
            int c4   = cidx & 15;
            float4 vv = *(const float4*)&g_V[(base + k0 + kk) * DH + c4 * 4];
            int chunk = (kk >> 2) ^ c4;   // j>>2 == c4
            int word  = kk & 3;
            Vst[(4 * c4 + 0) * 64 + (chunk << 2) + word] = vv.x;
            Vst[(4 * c4 + 1) * 64 + (chunk << 2) + word] = vv.y;
            Vst[(4 * c4 + 2) * 64 + (chunk << 2) + word] = vv.z;
            Vst[(4 * c4 + 3) * 64 + (chunk << 2) + word] = vv.w;
        }
        __syncthreads();

        // ---- S = Q @ K^T, packed over d ----
        u64 acc[8][4] = {};
        #pragma unroll 2
        for (int dc = 0; dc < 16; dc++) {
            u64 kp[4][2];
            #pragma unroll
            for (int j = 0; j < 4; j++) {
                ulonglong2 kv = *(const ulonglong2*)&Ks[(4 * tx + j) * 64 + ((dc ^ tx) << 2)];
                kp[j][0] = kv.x; kp[j][1] = kv.y;
            }
            #pragma unroll
            for (int i = 0; i < 8; i++) {
                ulonglong2 qv = *(const ulonglong2*)&Qs[(8 * ty + i) * 68 + dc * 4];
                #pragma unroll
                for (int j = 0; j < 4; j++) {
                    fma2(acc[i][j], qv.x, kp[j][0]);
                    fma2(acc[i][j], qv.y, kp[j][1]);
                }
            }
        }

        // ---- online softmax, write P ----
        float scl[8];
        #pragma unroll
        for (int i = 0; i < 8; i++) {
            float s0 = fold2(acc[i][0]);
            float s1 = fold2(acc[i][1]);
            float s2 = fold2(acc[i][2]);
            float s3 = fold2(acc[i][3]);
            float mi = fmaxf(fmaxf(s0, s1), fmaxf(s2, s3));
            #pragma unroll
            for (int off = 8; off >= 1; off >>= 1)
                mi = fmaxf(mi, __shfl_xor_sync(0xffffffffu, mi, off));
            float mnew = fmaxf(mrow[i], mi);
            scl[i] = __expf(mrow[i] - mnew);
            mrow[i] = mnew;
            float e0 = __expf(s0 - mnew);
            float e1 = __expf(s1 - mnew);
            float e2 = __expf(s2 - mnew);
            float e3 = __expf(s3 - mnew);
            float li = e0 + e1 + e2 + e3;
            #pragma unroll
            for (int off = 8; off >= 1; off >>= 1)
                li += __shfl_xor_sync(0xffffffffu, li, off);
            lrow[i] = lrow[i] * scl[i] + li;
            *(float4*)&Ps[(8 * ty + i) * 68 + 4 * tx] = make_float4(e0, e1, e2, e3);
        }
        __syncthreads();

        // ---- O = O*scl + P @ V, packed over kk ----
        #pragma unroll
        for (int i = 0; i < 8; i++)
            #pragma unroll
            for (int j = 0; j < 4; j++) acc[i][j] = 0ull;

        #pragma unroll 2
        for (int kc = 0; kc < 16; kc++) {
            u64 vp[4][2];
            #pragma unroll
            for (int j = 0; j < 4; j++) {
                ulonglong2 vv = *(const ulonglong2*)&Vst[(4 * tx + j) * 64 + ((kc ^ tx) << 2)];
                vp[j][0] = vv.x; vp[j][1] = vv.y;
            }
            #pragma unroll
            for (int i = 0; i < 8; i++) {
                ulonglong2 pv = *(const ulonglong2*)&Ps[(8 * ty + i) * 68 + kc * 4];
                #pragma unroll
                for (int j = 0; j < 4; j++) {
                    fma2(acc[i][j], pv.x, vp[j][0]);
                    fma2(acc[i][j], pv.y, vp[j][1]);
                }
            }
        }
        #pragma unroll
        for (int i = 0; i < 8; i++)
            #pragma unroll
            for (int j = 0; j < 4; j++)
                o[i][j] = o[i][j] * scl[i] + fold2(acc[i][j]);
    }

    // epilogue: normalize, apply mask
    #pragma unroll
    for (int i = 0; i < 8; i++) {
        int q = q0 + 8 * ty + i;
        float mv  = mask[base + q];
        float inv = mv / lrow[i];
        float4 r = make_float4(o[i][0] * inv, o[i][1] * inv,
                               o[i][2] * inv, o[i][3] * inv);
        *(float4*)&out[(size_t)(base + q) * DH + 4 * tx] = r;
    }
}

// ---------------------------------------------------------------------------
extern "C" void kernel_launch(void* const* d_in, const int* in_sizes, int n_in,
                              void* d_out, int out_size)
{
    const float* X    = (const float*)d_in[0];
    const float* mask = (const float*)d_in[1];
    const float* Wq   = (const float*)d_in[2];
    const float* bq   = (const float*)d_in[3];
    const float* Wk   = (const float*)d_in[4];
    const float* bk   = (const float*)d_in[5];
    const float* Wv   = (const float*)d_in[6];
    const float* bv   = (const float*)d_in[7];

    const int smem_attn = (128 * 68 + 64 * 64 + 64 * 64 + 128 * 68) * sizeof(float); // 102400
    cudaFuncSetAttribute(attn_kernel,
                         cudaFuncAttributeMaxDynamicSharedMemorySize, smem_attn);

    qkv_kernel<<<dim3(MROWS / 64, 3), 256>>>(X, Wq, bq, Wk, bk, Wv, bv);
    attn_kernel<<<dim3(SS / 128, BB), 256, smem_attn>>>(mask, (float*)d_out);
}